// round 2
// baseline (speedup 1.0000x reference)
#include <cuda_runtime.h>

// ---------------- problem constants ----------------
#define N_AG 2048           // B*Amax = 32*64
#define T_K 16
#define D_F 10
#define E_F 128
#define H_F 512
#define M3 (E_F * D_F)      // 1280
#define ND (N_AG * D_F)     // 20480
#define NPTS 60             // 15 steps x 4 stages
#define NE (N_AG * E_F)     // 262144

// ---------------- scratch (no cudaMalloc allowed) ----------------
__device__ float g_M[T_K * ND];
__device__ float g_dX[NPTS * ND];
__device__ float g_z[NE];
__device__ float g_zin[NE];
__device__ float g_k1[NE];
__device__ float g_k2[NE];
__device__ float g_k3[NE];
__device__ float g_k4[NE];
__device__ float g_y0[N_AG * H_F];
__device__ float g_y1[N_AG * H_F];
__device__ float g_y2[N_AG * H_F];
__device__ float g_y3[N_AG * M3];

// ---------------- helpers ----------------
__device__ __forceinline__ unsigned long long dup2(float v) {
    unsigned int u = __float_as_uint(v);
    return ((unsigned long long)u << 32) | (unsigned long long)u;
}

__device__ __forceinline__ float fast_tanh(float x) {
    x = fminf(fmaxf(x, -15.f), 15.f);
    float e = __expf(-2.f * x);
    return (1.f - e) * __frcp_rn(1.f + e);
}

// ---------------- spline: natural cubic second derivatives (Thomas) ----------------
__global__ void spline_kernel(const float* __restrict__ t, const float* __restrict__ x) {
    int col = blockIdx.x * blockDim.x + threadIdx.x;
    if (col >= ND) return;
    int n = col / D_F, d = col % D_F;

    float tv[T_K];
#pragma unroll
    for (int i = 0; i < T_K; i++) tv[i] = t[i];
    float xv[T_K];
#pragma unroll
    for (int i = 0; i < T_K; i++) xv[i] = x[(n * T_K + i) * D_F + d];
    float h[T_K - 1];
#pragma unroll
    for (int i = 0; i < T_K - 1; i++) h[i] = tv[i + 1] - tv[i];

    float cp[T_K], dp[T_K];
    cp[0] = 0.f; dp[0] = 0.f;   // row0: diag=1, upper=0, rhs=0
#pragma unroll
    for (int i = 1; i < T_K - 1; i++) {
        float rhs = 6.f * ((xv[i + 1] - xv[i]) / h[i] - (xv[i] - xv[i - 1]) / h[i - 1]);
        float m = 2.f * (h[i - 1] + h[i]) - h[i - 1] * cp[i - 1];
        float inv = 1.f / m;
        cp[i] = h[i] * inv;
        dp[i] = (rhs - h[i - 1] * dp[i - 1]) * inv;
    }
    float Mv[T_K];
    Mv[T_K - 1] = 0.f;          // last row: diag=1, lower=0, rhs=0
#pragma unroll
    for (int i = T_K - 2; i >= 0; i--) Mv[i] = dp[i] - cp[i] * Mv[i + 1];
#pragma unroll
    for (int i = 0; i < T_K; i++) g_M[i * ND + col] = Mv[i];
}

// ---------------- dX/dt at all 60 RK sample times ----------------
__global__ void dx_kernel(const float* __restrict__ t, const float* __restrict__ x) {
    int idx = blockIdx.x * blockDim.x + threadIdx.x;
    if (idx >= NPTS * ND) return;
    int pt = idx / ND, col = idx - pt * ND;
    int n = col / D_F, d = col - n * D_F;
    int k = pt >> 2, j = pt & 3;

    float t0 = t[k], t1 = t[k + 1];
    float hs = t1 - t0;
    float s;
    if (j == 0) s = t0;
    else if (j == 1) s = t0 + hs / 3.0f;
    else if (j == 2) s = t0 + 2.0f * hs / 3.0f;
    else s = t1;

    int cnt = 0;
#pragma unroll
    for (int i = 0; i < T_K; i++) cnt += (t[i] <= s) ? 1 : 0;
    int i = min(max(cnt - 1, 0), T_K - 2);

    float hi = t[i + 1] - t[i];
    float xi  = x[(n * T_K + i) * D_F + d];
    float xi1 = x[(n * T_K + i + 1) * D_F + d];
    float Mi  = g_M[i * ND + col];
    float Mi1 = g_M[(i + 1) * ND + col];
    float u = s - t[i];
    float b = (xi1 - xi) / hi - hi * (2.0f * Mi + Mi1) / 6.0f;
    g_dX[idx] = b + Mi * u + (Mi1 - Mi) * (u * u) / (2.0f * hi);
}

// ---------------- z0 = xs[0] @ W_embed^T + b_embed ----------------
__global__ void z0_kernel(const float* __restrict__ x, const float* __restrict__ We,
                          const float* __restrict__ be) {
    int idx = blockIdx.x * blockDim.x + threadIdx.x;
    if (idx >= NE) return;
    int n = idx / E_F, e = idx - n * E_F;
    float acc = be[e];
#pragma unroll
    for (int d = 0; d < D_F; d++) acc += x[n * T_K * D_F + d] * We[e * D_F + d];
    g_z[idx] = acc;
}

// ---------------- fp32 GEMM: C = act(A(NxK) @ W(MxK)^T + bias), f32x2 packed ----------------
// BM=128, BN=64, BK=16, 256 threads, per-thread 8x4 (as 4 row-pairs x 4 cols)
template <int ACT>  // 0 = relu, 1 = tanh
__global__ void __launch_bounds__(256) gemm_kernel(
    const float* __restrict__ A, const float* __restrict__ W,
    const float* __restrict__ bias, float* __restrict__ C, int K, int M)
{
    constexpr int BM = 128, BN = 64, BK = 16;
    constexpr int AP = BM + 4;
    constexpr int BP = BN + 1;
    __shared__ float As[2][BK][AP];
    __shared__ unsigned long long Bs[2][BK][BP];

    const int tid = threadIdx.x;
    const int rowBase = blockIdx.y * BM;
    const int colBase = blockIdx.x * BN;
    const int lr = tid >> 2;          // 0..63
    const int lc = (tid & 3) * 4;     // 0,4,8,12
    const int ty = tid >> 4;          // 0..15
    const int tx = tid & 15;          // 0..15

    const float* Aptr = A + (size_t)(rowBase + lr) * K + lc;
    const float* Wptr = W + (size_t)(colBase + lr) * K + lc;

    unsigned long long acc[4][4];
#pragma unroll
    for (int i = 0; i < 4; i++)
#pragma unroll
        for (int j = 0; j < 4; j++) acc[i][j] = 0ULL;

    float4 ra0 = *(const float4*)(Aptr);
    float4 ra1 = *(const float4*)(Aptr + 64 * K);
    float4 rb  = *(const float4*)(Wptr);

    // stage tile 0 into buffer 0
    As[0][lc + 0][lr] = ra0.x; As[0][lc + 1][lr] = ra0.y;
    As[0][lc + 2][lr] = ra0.z; As[0][lc + 3][lr] = ra0.w;
    As[0][lc + 0][lr + 64] = ra1.x; As[0][lc + 1][lr + 64] = ra1.y;
    As[0][lc + 2][lr + 64] = ra1.z; As[0][lc + 3][lr + 64] = ra1.w;
    Bs[0][lc + 0][lr] = dup2(rb.x); Bs[0][lc + 1][lr] = dup2(rb.y);
    Bs[0][lc + 2][lr] = dup2(rb.z); Bs[0][lc + 3][lr] = dup2(rb.w);
    __syncthreads();

    const int nk = K / BK;
    int buf = 0;
    for (int kt = 0; kt < nk; kt++) {
        if (kt + 1 < nk) {
            const float* Ap = Aptr + (kt + 1) * BK;
            ra0 = *(const float4*)(Ap);
            ra1 = *(const float4*)(Ap + 64 * K);
            rb  = *(const float4*)(Wptr + (kt + 1) * BK);
        }
#pragma unroll
        for (int kk = 0; kk < BK; kk++) {
            unsigned long long a2[4], b2[4];
#pragma unroll
            for (int i = 0; i < 4; i++)
                a2[i] = *(const unsigned long long*)&As[buf][kk][ty * 8 + 2 * i];
#pragma unroll
            for (int j = 0; j < 4; j++)
                b2[j] = Bs[buf][kk][tx * 4 + j];
#pragma unroll
            for (int i = 0; i < 4; i++)
#pragma unroll
                for (int j = 0; j < 4; j++)
                    asm("fma.rn.f32x2 %0, %1, %2, %0;"
                        : "+l"(acc[i][j]) : "l"(a2[i]), "l"(b2[j]));
        }
        if (kt + 1 < nk) {
            int nb = buf ^ 1;
            As[nb][lc + 0][lr] = ra0.x; As[nb][lc + 1][lr] = ra0.y;
            As[nb][lc + 2][lr] = ra0.z; As[nb][lc + 3][lr] = ra0.w;
            As[nb][lc + 0][lr + 64] = ra1.x; As[nb][lc + 1][lr + 64] = ra1.y;
            As[nb][lc + 2][lr + 64] = ra1.z; As[nb][lc + 3][lr + 64] = ra1.w;
            Bs[nb][lc + 0][lr] = dup2(rb.x); Bs[nb][lc + 1][lr] = dup2(rb.y);
            Bs[nb][lc + 2][lr] = dup2(rb.z); Bs[nb][lc + 3][lr] = dup2(rb.w);
            __syncthreads();
            buf = nb;
        }
    }

#pragma unroll
    for (int j = 0; j < 4; j++) {
        int col = colBase + tx * 4 + j;
        float bv = bias[col];
#pragma unroll
        for (int i = 0; i < 4; i++) {
            int row = rowBase + ty * 8 + 2 * i;
            float lo = __uint_as_float((unsigned int)(acc[i][j])) + bv;
            float hi = __uint_as_float((unsigned int)(acc[i][j] >> 32)) + bv;
            if (ACT == 0) { lo = fmaxf(lo, 0.f); hi = fmaxf(hi, 0.f); }
            else          { lo = fast_tanh(lo);  hi = fast_tanh(hi); }
            C[(size_t)row * M + col] = lo;
            C[(size_t)(row + 1) * M + col] = hi;
        }
    }
}

// ---------------- einsum: k[n,e] = sum_d y3[n, e*D+d] * dX[pt, n, d] ----------------
__global__ void einsum_kernel(int pt, float* __restrict__ kout) {
    int idx = blockIdx.x * blockDim.x + threadIdx.x;
    if (idx >= NE) return;
    int n = idx / E_F, e = idx - n * E_F;
    const float* y = &g_y3[(size_t)n * M3 + e * D_F];
    const float* dx = &g_dX[(size_t)pt * ND + n * D_F];
    float acc = 0.f;
#pragma unroll
    for (int d = 0; d < D_F; d++) acc += y[d] * dx[d];
    kout[idx] = acc;
}

// ---------------- RK4 (3/8 rule) stage combines ----------------
__global__ void combine_kernel(const float* __restrict__ t, int k, int mode) {
    int idx = blockIdx.x * blockDim.x + threadIdx.x;
    if (idx >= NE) return;
    float hs = t[k + 1] - t[k];
    float z = g_z[idx];
    if (mode == 0) {
        g_zin[idx] = z + hs * g_k1[idx] / 3.0f;
    } else if (mode == 1) {
        g_zin[idx] = z + hs * (g_k2[idx] - g_k1[idx] / 3.0f);
    } else if (mode == 2) {
        g_zin[idx] = z + hs * (g_k1[idx] - g_k2[idx] + g_k3[idx]);
    } else {
        g_z[idx] = z + hs * (g_k1[idx] + 3.0f * (g_k2[idx] + g_k3[idx]) + g_k4[idx]) / 8.0f;
    }
}

// ---------------- output with mask (mask delivered as int32) ----------------
__global__ void out_kernel(const int* __restrict__ mask, float* __restrict__ out) {
    int idx = blockIdx.x * blockDim.x + threadIdx.x;
    if (idx >= NE) return;
    int n = idx / E_F;
    out[idx] = (mask[n] != 0) ? g_z[idx] : 0.0f;
}

// ---------------- launcher ----------------
extern "C" void kernel_launch(void* const* d_in, const int* in_sizes, int n_in,
                              void* d_out, int out_size) {
    const float* t  = (const float*)d_in[0];
    const float* x  = (const float*)d_in[1];
    const int*   mask = (const int*)d_in[2];
    const float* We = (const float*)d_in[3];
    const float* be = (const float*)d_in[4];
    const float* W0 = (const float*)d_in[5];
    const float* b0 = (const float*)d_in[6];
    const float* W1 = (const float*)d_in[7];
    const float* b1 = (const float*)d_in[8];
    const float* W2 = (const float*)d_in[9];
    const float* b2 = (const float*)d_in[10];
    const float* W3 = (const float*)d_in[11];
    const float* b3 = (const float*)d_in[12];

    float *z, *zin, *y0, *y1, *y2, *y3, *k1, *k2, *k3, *k4;
    cudaGetSymbolAddress((void**)&z,   g_z);
    cudaGetSymbolAddress((void**)&zin, g_zin);
    cudaGetSymbolAddress((void**)&y0,  g_y0);
    cudaGetSymbolAddress((void**)&y1,  g_y1);
    cudaGetSymbolAddress((void**)&y2,  g_y2);
    cudaGetSymbolAddress((void**)&y3,  g_y3);
    cudaGetSymbolAddress((void**)&k1,  g_k1);
    cudaGetSymbolAddress((void**)&k2,  g_k2);
    cudaGetSymbolAddress((void**)&k3,  g_k3);
    cudaGetSymbolAddress((void**)&k4,  g_k4);
    float* kb[4] = {k1, k2, k3, k4};

    spline_kernel<<<(ND + 255) / 256, 256>>>(t, x);
    dx_kernel<<<(NPTS * ND + 255) / 256, 256>>>(t, x);
    z0_kernel<<<(NE + 255) / 256, 256>>>(x, We, be);

    dim3 gH(H_F / 64, N_AG / 128);   // (8, 16)
    dim3 g3(M3 / 64, N_AG / 128);    // (20, 16)
    int eb = (NE + 255) / 256;

    for (int k = 0; k < T_K - 1; k++) {
        for (int stage = 0; stage < 4; stage++) {
            const float* zsrc = (stage == 0) ? z : zin;
            gemm_kernel<0><<<gH, 256>>>(zsrc, W0, b0, y0, E_F, H_F);
            gemm_kernel<0><<<gH, 256>>>(y0, W1, b1, y1, H_F, H_F);
            gemm_kernel<0><<<gH, 256>>>(y1, W2, b2, y2, H_F, H_F);
            gemm_kernel<1><<<g3, 256>>>(y2, W3, b3, y3, H_F, M3);
            einsum_kernel<<<eb, 256>>>(k * 4 + stage, kb[stage]);
            combine_kernel<<<eb, 256>>>(t, k, stage);
        }
    }
    out_kernel<<<eb, 256>>>(mask, (float*)d_out);
}

// round 5
// speedup vs baseline: 3.4061x; 3.4061x over previous
#include <cuda_runtime.h>
#include <cuda_bf16.h>
#include <cstdint>

// ---------------- problem constants ----------------
#define N_AG 2048           // B*Amax
#define T_K 16
#define D_F 10
#define E_F 128
#define H_F 512
#define M3 (E_F * D_F)      // 1280
#define ND (N_AG * D_F)     // 20480
#define NPTS 60
#define NE (N_AG * E_F)     // 262144

// ---------------- scratch ----------------
__device__ float g_M[T_K * ND];
__device__ float g_dX[NPTS * ND];
__device__ float g_z[NE];
__device__ float g_k1[NE];
__device__ float g_k2[NE];
__device__ float g_k3[NE];
__device__ float g_y3[N_AG * M3];

#define BF16A __device__ __align__(16) __nv_bfloat16
BF16A g_zh[NE],   g_zl[NE];
BF16A g_zinh[NE], g_zinl[NE];
BF16A g_y0h[N_AG * H_F], g_y0l[N_AG * H_F];
BF16A g_y1h[N_AG * H_F], g_y1l[N_AG * H_F];
BF16A g_y2h[N_AG * H_F], g_y2l[N_AG * H_F];
BF16A g_W0h[H_F * E_F], g_W0l[H_F * E_F];
BF16A g_W1h[H_F * H_F], g_W1l[H_F * H_F];
BF16A g_W2h[H_F * H_F], g_W2l[H_F * H_F];
BF16A g_W3h[M3 * H_F],  g_W3l[M3 * H_F];

// ---------------- helpers ----------------
__device__ __forceinline__ uint32_t smem_u32(const void* p) {
    uint32_t a;
    asm("{ .reg .u64 t; cvta.to.shared.u64 t, %1; cvt.u32.u64 %0, t; }" : "=r"(a) : "l"(p));
    return a;
}
__device__ __forceinline__ void cp16(uint32_t s, const void* g) {
    asm volatile("cp.async.cg.shared.global [%0], [%1], 16;" :: "r"(s), "l"(g));
}
__device__ __forceinline__ uint32_t lds32(uint32_t a) {
    uint32_t v;
    asm volatile("ld.shared.b32 %0, [%1];" : "=r"(v) : "r"(a));
    return v;
}
__device__ __forceinline__ void mma16816(float& c0, float& c1, float& c2, float& c3,
                                         uint32_t a0, uint32_t a1, uint32_t a2, uint32_t a3,
                                         uint32_t b0, uint32_t b1) {
    asm volatile("mma.sync.aligned.m16n8k16.row.col.f32.bf16.bf16.f32 "
                 "{%0,%1,%2,%3},{%4,%5,%6,%7},{%8,%9},{%0,%1,%2,%3};"
                 : "+f"(c0), "+f"(c1), "+f"(c2), "+f"(c3)
                 : "r"(a0), "r"(a1), "r"(a2), "r"(a3), "r"(b0), "r"(b1));
}
__device__ __forceinline__ uint32_t pack_bf16(float lo, float hi) {
    uint32_t r;
    asm("cvt.rn.bf16x2.f32 %0, %1, %2;" : "=r"(r) : "f"(hi), "f"(lo));
    return r;
}
__device__ __forceinline__ float fast_tanh(float x) {
    x = fminf(fmaxf(x, -15.f), 15.f);
    float e = __expf(-2.f * x);
    return (1.f - e) * __frcp_rn(1.f + e);
}

// smem layout (bytes, per buffer): padded row stride 40 bf16 = 80 B (conflict-free)
#define STRIDE 40
#define OFF_AH 0
#define OFF_AL 10240
#define OFF_BH 20480
#define OFF_BL 25600
#define BUF_B  30720
#define SMEM_BYTES (2 * BUF_B)      // 61440

// ---------------- split-bf16 HMMA GEMM: C = act(A(NxK) @ W(MoutxK)^T + bias) ----------
// CTA 128x64, BK=32, 8 warps 4(M)x2(N), warp tile 32x32.
// D = Ah*Bh + Ah*Bl + Al*Bh with fp32 accum -> fp32-class accuracy.
template <int ACT>  // 0: relu + split bf16 out; 1: tanh + fp32 out
__global__ void __launch_bounds__(256) mma_gemm(
    const __nv_bfloat16* __restrict__ Ah, const __nv_bfloat16* __restrict__ Al,
    const __nv_bfloat16* __restrict__ Bh, const __nv_bfloat16* __restrict__ Bl,
    const float* __restrict__ bias,
    __nv_bfloat16* __restrict__ Ch, __nv_bfloat16* __restrict__ Cl,
    float* __restrict__ Cf, int K, int Mout)
{
    extern __shared__ char smem[];
    const uint32_t sb = smem_u32(smem);
    const int tid = threadIdx.x, wid = tid >> 5, lid = tid & 31;
    const int rowBase = blockIdx.y * 128;
    const int colBase = blockIdx.x * 64;
    const int warpM = (wid & 3) * 32;
    const int warpN = (wid >> 2) * 32;
    const int grp = lid >> 2, q = lid & 3;

    // per-thread load assignments
    const int ar0 = tid >> 1;                 // A row 0..127 (each row: 2 threads)
    const int ac0 = (tid & 1) * 16;           // starting half within 32-half row piece
    const int br = tid >> 2, bc = tid & 3;    // B: 64 rows x 4 threads, 8 halves each

    const __nv_bfloat16* gAh = Ah + (size_t)(rowBase + ar0) * K + ac0;
    const __nv_bfloat16* gAl = Al + (size_t)(rowBase + ar0) * K + ac0;
    const __nv_bfloat16* gBh = Bh + (size_t)(colBase + br) * K + bc * 8;
    const __nv_bfloat16* gBl = Bl + (size_t)(colBase + br) * K + bc * 8;

    const uint32_t sAh = sb + OFF_AH + (ar0 * STRIDE + ac0) * 2;
    const uint32_t sAl = sb + OFF_AL + (ar0 * STRIDE + ac0) * 2;
    const uint32_t sBh = sb + OFF_BH + (br * STRIDE + bc * 8) * 2;
    const uint32_t sBl = sb + OFF_BL + (br * STRIDE + bc * 8) * 2;

    float c[2][4][4];
#pragma unroll
    for (int mi = 0; mi < 2; mi++)
#pragma unroll
        for (int ni = 0; ni < 4; ni++)
#pragma unroll
            for (int r = 0; r < 4; r++) c[mi][ni][r] = 0.f;

    const int NK = K >> 5;

    // prologue: load tile 0 into buffer 0  (each A thread: 16 halves = 2 x 16B)
    cp16(sAh,      gAh);      cp16(sAh + 16, gAh + 8);
    cp16(sAl,      gAl);      cp16(sAl + 16, gAl + 8);
    cp16(sBh,      gBh);      cp16(sBl,      gBl);
    asm volatile("cp.async.commit_group;");

    for (int kt = 0; kt < NK; kt++) {
        if (kt + 1 < NK) {
            const int k0 = (kt + 1) << 5;
            const uint32_t bo = ((kt + 1) & 1) * BUF_B;
            cp16(sAh + bo,      gAh + k0);  cp16(sAh + bo + 16, gAh + k0 + 8);
            cp16(sAl + bo,      gAl + k0);  cp16(sAl + bo + 16, gAl + k0 + 8);
            cp16(sBh + bo,      gBh + k0);  cp16(sBl + bo,      gBl + k0);
        }
        asm volatile("cp.async.commit_group;");
        asm volatile("cp.async.wait_group 1;");
        __syncthreads();

        const uint32_t aBase = sb + (kt & 1) * BUF_B;
#pragma unroll
        for (int kk = 0; kk < 32; kk += 16) {
            uint32_t ah[2][4], al[2][4], bh[4][2], bl[4][2];
#pragma unroll
            for (int mi = 0; mi < 2; mi++) {
                const int r0 = warpM + mi * 16 + grp;
                const uint32_t o0 = aBase + (r0 * STRIDE + kk + q * 2) * 2;
                const uint32_t o1 = aBase + ((r0 + 8) * STRIDE + kk + q * 2) * 2;
                ah[mi][0] = lds32(OFF_AH + o0);  ah[mi][1] = lds32(OFF_AH + o1);
                ah[mi][2] = lds32(OFF_AH + o0 + 16); ah[mi][3] = lds32(OFF_AH + o1 + 16);
                al[mi][0] = lds32(OFF_AL + o0);  al[mi][1] = lds32(OFF_AL + o1);
                al[mi][2] = lds32(OFF_AL + o0 + 16); al[mi][3] = lds32(OFF_AL + o1 + 16);
            }
#pragma unroll
            for (int ni = 0; ni < 4; ni++) {
                const int n0 = warpN + ni * 8 + grp;
                const uint32_t o = aBase + (n0 * STRIDE + kk + q * 2) * 2;
                bh[ni][0] = lds32(OFF_BH + o);  bh[ni][1] = lds32(OFF_BH + o + 16);
                bl[ni][0] = lds32(OFF_BL + o);  bl[ni][1] = lds32(OFF_BL + o + 16);
            }
#pragma unroll
            for (int mi = 0; mi < 2; mi++)
#pragma unroll
                for (int ni = 0; ni < 4; ni++) {
                    float* cc = c[mi][ni];
                    mma16816(cc[0], cc[1], cc[2], cc[3],
                             ah[mi][0], ah[mi][1], ah[mi][2], ah[mi][3],
                             bh[ni][0], bh[ni][1]);
                    mma16816(cc[0], cc[1], cc[2], cc[3],
                             ah[mi][0], ah[mi][1], ah[mi][2], ah[mi][3],
                             bl[ni][0], bl[ni][1]);
                    mma16816(cc[0], cc[1], cc[2], cc[3],
                             al[mi][0], al[mi][1], al[mi][2], al[mi][3],
                             bh[ni][0], bh[ni][1]);
                }
        }
        __syncthreads();
    }

    // ---------------- epilogue ----------------
#pragma unroll
    for (int ni = 0; ni < 4; ni++) {
        const int col = colBase + warpN + ni * 8 + q * 2;
        const float bv0 = bias[col], bv1 = bias[col + 1];
#pragma unroll
        for (int mi = 0; mi < 2; mi++) {
            const int row0 = rowBase + warpM + mi * 16 + grp;
            float v00 = c[mi][ni][0] + bv0, v01 = c[mi][ni][1] + bv1;   // row0
            float v10 = c[mi][ni][2] + bv0, v11 = c[mi][ni][3] + bv1;   // row0+8
            if (ACT == 0) {
                v00 = fmaxf(v00, 0.f); v01 = fmaxf(v01, 0.f);
                v10 = fmaxf(v10, 0.f); v11 = fmaxf(v11, 0.f);
                uint32_t h0 = pack_bf16(v00, v01);
                uint32_t h1 = pack_bf16(v10, v11);
                float r00 = v00 - __uint_as_float(h0 << 16);
                float r01 = v01 - __uint_as_float(h0 & 0xFFFF0000u);
                float r10 = v10 - __uint_as_float(h1 << 16);
                float r11 = v11 - __uint_as_float(h1 & 0xFFFF0000u);
                *(uint32_t*)(Ch + (size_t)row0 * Mout + col) = h0;
                *(uint32_t*)(Ch + (size_t)(row0 + 8) * Mout + col) = h1;
                *(uint32_t*)(Cl + (size_t)row0 * Mout + col) = pack_bf16(r00, r01);
                *(uint32_t*)(Cl + (size_t)(row0 + 8) * Mout + col) = pack_bf16(r10, r11);
            } else {
                float2 o0 = make_float2(fast_tanh(v00), fast_tanh(v01));
                float2 o1 = make_float2(fast_tanh(v10), fast_tanh(v11));
                *(float2*)(Cf + (size_t)row0 * Mout + col) = o0;
                *(float2*)(Cf + (size_t)(row0 + 8) * Mout + col) = o1;
            }
        }
    }
}

// ---------------- weight split ----------------
__global__ void wsplit(const float* __restrict__ s, __nv_bfloat16* __restrict__ h,
                       __nv_bfloat16* __restrict__ l, int n) {
    int idx = blockIdx.x * blockDim.x + threadIdx.x;
    if (idx >= n) return;
    float v = s[idx];
    __nv_bfloat16 bh = __float2bfloat16(v);
    h[idx] = bh;
    l[idx] = __float2bfloat16(v - __bfloat162float(bh));
}

// ---------------- spline ----------------
__global__ void spline_kernel(const float* __restrict__ t, const float* __restrict__ x) {
    int col = blockIdx.x * blockDim.x + threadIdx.x;
    if (col >= ND) return;
    int n = col / D_F, d = col % D_F;
    float tv[T_K];
#pragma unroll
    for (int i = 0; i < T_K; i++) tv[i] = t[i];
    float xv[T_K];
#pragma unroll
    for (int i = 0; i < T_K; i++) xv[i] = x[(n * T_K + i) * D_F + d];
    float h[T_K - 1];
#pragma unroll
    for (int i = 0; i < T_K - 1; i++) h[i] = tv[i + 1] - tv[i];
    float cp[T_K], dp[T_K];
    cp[0] = 0.f; dp[0] = 0.f;
#pragma unroll
    for (int i = 1; i < T_K - 1; i++) {
        float rhs = 6.f * ((xv[i + 1] - xv[i]) / h[i] - (xv[i] - xv[i - 1]) / h[i - 1]);
        float m = 2.f * (h[i - 1] + h[i]) - h[i - 1] * cp[i - 1];
        float inv = 1.f / m;
        cp[i] = h[i] * inv;
        dp[i] = (rhs - h[i - 1] * dp[i - 1]) * inv;
    }
    float Mv[T_K];
    Mv[T_K - 1] = 0.f;
#pragma unroll
    for (int i = T_K - 2; i >= 0; i--) Mv[i] = dp[i] - cp[i] * Mv[i + 1];
#pragma unroll
    for (int i = 0; i < T_K; i++) g_M[i * ND + col] = Mv[i];
}

// ---------------- dX/dt ----------------
__global__ void dx_kernel(const float* __restrict__ t, const float* __restrict__ x) {
    int idx = blockIdx.x * blockDim.x + threadIdx.x;
    if (idx >= NPTS * ND) return;
    int pt = idx / ND, col = idx - pt * ND;
    int n = col / D_F, d = col - n * D_F;
    int k = pt >> 2, j = pt & 3;
    float t0 = t[k], t1 = t[k + 1];
    float hs = t1 - t0;
    float s;
    if (j == 0) s = t0;
    else if (j == 1) s = t0 + hs / 3.0f;
    else if (j == 2) s = t0 + 2.0f * hs / 3.0f;
    else s = t1;
    int cnt = 0;
#pragma unroll
    for (int i = 0; i < T_K; i++) cnt += (t[i] <= s) ? 1 : 0;
    int i = min(max(cnt - 1, 0), T_K - 2);
    float hi = t[i + 1] - t[i];
    float xi  = x[(n * T_K + i) * D_F + d];
    float xi1 = x[(n * T_K + i + 1) * D_F + d];
    float Mi  = g_M[i * ND + col];
    float Mi1 = g_M[(i + 1) * ND + col];
    float u = s - t[i];
    float b = (xi1 - xi) / hi - hi * (2.0f * Mi + Mi1) / 6.0f;
    g_dX[idx] = b + Mi * u + (Mi1 - Mi) * (u * u) / (2.0f * hi);
}

// ---------------- z0 ----------------
__global__ void z0_kernel(const float* __restrict__ x, const float* __restrict__ We,
                          const float* __restrict__ be) {
    int idx = blockIdx.x * blockDim.x + threadIdx.x;
    if (idx >= NE) return;
    int n = idx / E_F, e = idx - n * E_F;
    float acc = be[e];
#pragma unroll
    for (int d = 0; d < D_F; d++) acc += x[n * T_K * D_F + d] * We[e * D_F + d];
    g_z[idx] = acc;
    __nv_bfloat16 h = __float2bfloat16(acc);
    g_zh[idx] = h;
    g_zl[idx] = __float2bfloat16(acc - __bfloat162float(h));
}

// ---------------- fused einsum + RK combine ----------------
__global__ void vf_combine(const float* __restrict__ t, int k, int mode) {
    int idx = blockIdx.x * blockDim.x + threadIdx.x;
    if (idx >= NE) return;
    int n = idx >> 7, e = idx & 127;
    const float* y  = g_y3 + (size_t)n * M3 + e * D_F;
    const float* dx = g_dX + (size_t)(k * 4 + mode) * ND + n * D_F;
    float kv = 0.f;
#pragma unroll
    for (int d = 0; d < D_F; d++) kv += y[d] * dx[d];
    float hs = t[k + 1] - t[k];
    float z = g_z[idx];
    float zn;
    if (mode == 0)      { g_k1[idx] = kv; zn = z + hs * kv / 3.0f; }
    else if (mode == 1) { g_k2[idx] = kv; zn = z + hs * (kv - g_k1[idx] / 3.0f); }
    else if (mode == 2) { g_k3[idx] = kv; zn = z + hs * (g_k1[idx] - g_k2[idx] + kv); }
    else {
        zn = z + hs * (g_k1[idx] + 3.0f * (g_k2[idx] + g_k3[idx]) + kv) / 8.0f;
        g_z[idx] = zn;
    }
    __nv_bfloat16 h = __float2bfloat16(zn);
    __nv_bfloat16 l = __float2bfloat16(zn - __bfloat162float(h));
    if (mode == 3) { g_zh[idx] = h;   g_zl[idx] = l; }
    else           { g_zinh[idx] = h; g_zinl[idx] = l; }
}

// ---------------- output with mask ----------------
__global__ void out_kernel(const int* __restrict__ mask, float* __restrict__ out) {
    int idx = blockIdx.x * blockDim.x + threadIdx.x;
    if (idx >= NE) return;
    int n = idx / E_F;
    out[idx] = (mask[n] != 0) ? g_z[idx] : 0.0f;
}

// ---------------- launcher ----------------
extern "C" void kernel_launch(void* const* d_in, const int* in_sizes, int n_in,
                              void* d_out, int out_size) {
    const float* t  = (const float*)d_in[0];
    const float* x  = (const float*)d_in[1];
    const int*   mask = (const int*)d_in[2];
    const float* We = (const float*)d_in[3];
    const float* be = (const float*)d_in[4];
    const float* W0 = (const float*)d_in[5];
    const float* b0 = (const float*)d_in[6];
    const float* W1 = (const float*)d_in[7];
    const float* b1 = (const float*)d_in[8];
    const float* W2 = (const float*)d_in[9];
    const float* b2 = (const float*)d_in[10];
    const float* W3 = (const float*)d_in[11];
    const float* b3 = (const float*)d_in[12];

    cudaFuncSetAttribute(mma_gemm<0>, cudaFuncAttributeMaxDynamicSharedMemorySize, SMEM_BYTES);
    cudaFuncSetAttribute(mma_gemm<1>, cudaFuncAttributeMaxDynamicSharedMemorySize, SMEM_BYTES);

    __nv_bfloat16 *zh, *zl, *zinh, *zinl, *y0h, *y0l, *y1h, *y1l, *y2h, *y2l;
    __nv_bfloat16 *W0h, *W0l, *W1h, *W1l, *W2h, *W2l, *W3h, *W3l;
    float* y3;
    cudaGetSymbolAddress((void**)&zh, g_zh);     cudaGetSymbolAddress((void**)&zl, g_zl);
    cudaGetSymbolAddress((void**)&zinh, g_zinh); cudaGetSymbolAddress((void**)&zinl, g_zinl);
    cudaGetSymbolAddress((void**)&y0h, g_y0h);   cudaGetSymbolAddress((void**)&y0l, g_y0l);
    cudaGetSymbolAddress((void**)&y1h, g_y1h);   cudaGetSymbolAddress((void**)&y1l, g_y1l);
    cudaGetSymbolAddress((void**)&y2h, g_y2h);   cudaGetSymbolAddress((void**)&y2l, g_y2l);
    cudaGetSymbolAddress((void**)&W0h, g_W0h);   cudaGetSymbolAddress((void**)&W0l, g_W0l);
    cudaGetSymbolAddress((void**)&W1h, g_W1h);   cudaGetSymbolAddress((void**)&W1l, g_W1l);
    cudaGetSymbolAddress((void**)&W2h, g_W2h);   cudaGetSymbolAddress((void**)&W2l, g_W2l);
    cudaGetSymbolAddress((void**)&W3h, g_W3h);   cudaGetSymbolAddress((void**)&W3l, g_W3l);
    cudaGetSymbolAddress((void**)&y3, g_y3);

    wsplit<<<(H_F * E_F + 255) / 256, 256>>>(W0, W0h, W0l, H_F * E_F);
    wsplit<<<(H_F * H_F + 255) / 256, 256>>>(W1, W1h, W1l, H_F * H_F);
    wsplit<<<(H_F * H_F + 255) / 256, 256>>>(W2, W2h, W2l, H_F * H_F);
    wsplit<<<(M3 * H_F + 255) / 256, 256>>>(W3, W3h, W3l, M3 * H_F);

    spline_kernel<<<(ND + 255) / 256, 256>>>(t, x);
    dx_kernel<<<(NPTS * ND + 255) / 256, 256>>>(t, x);
    z0_kernel<<<(NE + 255) / 256, 256>>>(x, We, be);

    dim3 gH(H_F / 64, N_AG / 128);   // (8, 16)
    dim3 g3(M3 / 64, N_AG / 128);    // (20, 16)
    int eb = (NE + 255) / 256;

    for (int k = 0; k < T_K - 1; k++) {
        for (int stage = 0; stage < 4; stage++) {
            const __nv_bfloat16* ah = (stage == 0) ? zh : zinh;
            const __nv_bfloat16* al = (stage == 0) ? zl : zinl;
            mma_gemm<0><<<gH, 256, SMEM_BYTES>>>(ah,  al,  W0h, W0l, b0, y0h, y0l, nullptr, E_F, H_F);
            mma_gemm<0><<<gH, 256, SMEM_BYTES>>>(y0h, y0l, W1h, W1l, b1, y1h, y1l, nullptr, H_F, H_F);
            mma_gemm<0><<<gH, 256, SMEM_BYTES>>>(y1h, y1l, W2h, W2l, b2, y2h, y2l, nullptr, H_F, H_F);
            mma_gemm<1><<<g3, 256, SMEM_BYTES>>>(y2h, y2l, W3h, W3l, b3, nullptr, nullptr, y3, H_F, M3);
            vf_combine<<<eb, 256>>>(t, k, stage);
        }
    }
    out_kernel<<<eb, 256>>>(mask, (float*)d_out);
}